// round 2
// baseline (speedup 1.0000x reference)
#include <cuda_runtime.h>
#include <math.h>

#define NN 50000
#define EE 800000
#define ET 850000        // EE + NN self loops
#define FNEG 0.2f

// ---------------- static device scratch (no allocation allowed) ----------------
__device__ float g_xw [NN * 128];    // per-layer x@W (layer2: [N,12])
__device__ float g_acc[NN * 128];    // linear part + scatter accumulation (layer2: [N,12])
__device__ float g_h  [NN * 128];    // activations between layers
__device__ float g_als[NN * 6];
__device__ float g_ald[NN * 6];
__device__ float g_nmax[NN * 6];
__device__ float g_nsum[NN * 6];
__device__ float g_ebuf[5100000];    // ET * 6 edge alpha / exp values
__device__ float g_lin2[NN * 2];     // layer2 linear part

// ---------------- helpers ----------------
__device__ __forceinline__ unsigned long long pk2(float x, float y) {
    unsigned long long r;
    asm("mov.b64 %0, {%1, %2};" : "=l"(r) : "f"(x), "f"(y));
    return r;
}
__device__ __forceinline__ void upk2(unsigned long long v, float &x, float &y) {
    asm("mov.b64 {%0, %1}, %2;" : "=f"(x), "=f"(y) : "l"(v));
}
__device__ __forceinline__ void atomicMaxFloat(float *addr, float v) {
    if (v >= 0.f) atomicMax((int *)addr, __float_as_int(v));
    else          atomicMin((unsigned int *)addr, __float_as_uint(v));
}
__device__ __forceinline__ void red_add_v4(float *p, float a, float b, float c, float d) {
    asm volatile("red.global.add.v4.f32 [%0], {%1,%2,%3,%4};"
                 :: "l"(p), "f"(a), "f"(b), "f"(c), "f"(d) : "memory");
}

// ---------------- dense GEMM: C[N,128] = A[N,128] @ B[128,128] -----------------
// blockIdx.y == 0: B = B0, C = g_xw ;  blockIdx.y == 1: B = B1, C = g_acc
// srcX: 1 -> A = Ain (input x), 0 -> A = g_h
__global__ __launch_bounds__(256) void gemm_dual(const float *__restrict__ Ain,
                                                 const float *__restrict__ B0,
                                                 const float *__restrict__ B1,
                                                 int srcX) {
    const float *A = srcX ? Ain : g_h;
    const float *B = (blockIdx.y == 0) ? B0 : B1;
    float *C       = (blockIdx.y == 0) ? g_xw : g_acc;

    __shared__ float As[16][128];   // [k][row]
    __shared__ float Bs[16][128];   // [k][col]

    int tid = threadIdx.x;
    int tr = tid >> 4, tc = tid & 15;
    int rowBase = blockIdx.x * 128;

    unsigned long long acc[8][4];
#pragma unroll
    for (int i = 0; i < 8; i++)
#pragma unroll
        for (int j = 0; j < 4; j++) acc[i][j] = 0ULL;

    for (int k0 = 0; k0 < 128; k0 += 16) {
        // load A tile (transpose into As[k][row])
#pragma unroll
        for (int t = 0; t < 2; t++) {
            int idx = tid + t * 256;          // 0..511 float4s
            int r = idx >> 2, kq = idx & 3;
            int grow = rowBase + r;
            float4 v = make_float4(0.f, 0.f, 0.f, 0.f);
            if (grow < NN) v = *(const float4 *)(A + grow * 128 + k0 + kq * 4);
            As[kq * 4 + 0][r] = v.x;
            As[kq * 4 + 1][r] = v.y;
            As[kq * 4 + 2][r] = v.z;
            As[kq * 4 + 3][r] = v.w;
        }
        // load B tile
#pragma unroll
        for (int t = 0; t < 2; t++) {
            int idx = tid + t * 256;
            int r = idx >> 5, cq = idx & 31;
            *((float4 *)&Bs[r][cq * 4]) = *(const float4 *)(B + (k0 + r) * 128 + cq * 4);
        }
        __syncthreads();
#pragma unroll
        for (int k = 0; k < 16; k++) {
            float4 a0 = *(const float4 *)&As[k][tr * 8];
            float4 a1 = *(const float4 *)&As[k][tr * 8 + 4];
            float4 b0 = *(const float4 *)&Bs[k][tc * 8];
            float4 b1 = *(const float4 *)&Bs[k][tc * 8 + 4];
            unsigned long long bp[4] = {pk2(b0.x, b0.y), pk2(b0.z, b0.w),
                                        pk2(b1.x, b1.y), pk2(b1.z, b1.w)};
            float av[8] = {a0.x, a0.y, a0.z, a0.w, a1.x, a1.y, a1.z, a1.w};
#pragma unroll
            for (int i = 0; i < 8; i++) {
                unsigned long long ap = pk2(av[i], av[i]);
#pragma unroll
                for (int j = 0; j < 4; j++)
                    asm("fma.rn.f32x2 %0, %1, %2, %0;"
                        : "+l"(acc[i][j]) : "l"(ap), "l"(bp[j]));
            }
        }
        __syncthreads();
    }
#pragma unroll
    for (int i = 0; i < 8; i++) {
        int row = rowBase + tr * 8 + i;
        if (row < NN) {
            float o[8];
#pragma unroll
            for (int j = 0; j < 4; j++) upk2(acc[i][j], o[j * 2], o[j * 2 + 1]);
            *(float4 *)(C + row * 128 + tc * 8)     = make_float4(o[0], o[1], o[2], o[3]);
            *(float4 *)(C + row * 128 + tc * 8 + 4) = make_float4(o[4], o[5], o[6], o[7]);
        }
    }
}

// ------------- per-node attention logits + softmax init (layers 0/1, H=4,C=32) --
__global__ void logits01(const float *__restrict__ a_s, const float *__restrict__ a_d) {
    int t = blockIdx.x * blockDim.x + threadIdx.x;
    if (t >= NN * 4) return;
    int n = t >> 2, h = t & 3;
    const float *xr = g_xw + n * 128 + h * 32;
    float s = 0.f, d = 0.f;
#pragma unroll
    for (int c = 0; c < 32; c++) {
        float v = xr[c];
        s += v * a_s[h * 32 + c];
        d += v * a_d[h * 32 + c];
    }
    g_als[t] = s;
    g_ald[t] = d;
    g_nmax[t] = __int_as_float(0xFF800000);  // -inf
    g_nsum[t] = 0.f;
}

// ------------- layer2 logits (H=6, C=2) + init + zero acc ----------------------
__global__ void logits2(const float *__restrict__ a_s, const float *__restrict__ a_d) {
    int t = blockIdx.x * blockDim.x + threadIdx.x;
    if (t >= NN * 6) return;
    int n = t / 6, h = t - n * 6;
    float x0 = g_xw[n * 12 + h * 2], x1 = g_xw[n * 12 + h * 2 + 1];
    g_als[t] = x0 * a_s[h * 2] + x1 * a_s[h * 2 + 1];
    g_ald[t] = x0 * a_d[h * 2] + x1 * a_d[h * 2 + 1];
    g_nmax[t] = __int_as_float(0xFF800000);
    g_nsum[t] = 0.f;
    g_acc[n * 12 + h * 2] = 0.f;
    g_acc[n * 12 + h * 2 + 1] = 0.f;
}

// ------------- edge pass 1: alpha + segment max --------------------------------
template <int H>
__global__ void epass1(const int *__restrict__ ei) {
    int t = blockIdx.x * blockDim.x + threadIdx.x;
    if (t >= ET * H) return;
    int e = t / H, h = t - e * H;
    int src, dst;
    if (e < EE) { src = ei[e]; dst = ei[EE + e]; } else { src = dst = e - EE; }
    float a = g_als[src * H + h] + g_ald[dst * H + h];
    a = a > 0.f ? a : FNEG * a;
    g_ebuf[t] = a;
    atomicMaxFloat(&g_nmax[dst * H + h], a);
}

// ------------- edge pass 2: exp + segment sum ----------------------------------
template <int H>
__global__ void epass2(const int *__restrict__ ei) {
    int t = blockIdx.x * blockDim.x + threadIdx.x;
    if (t >= ET * H) return;
    int e = t / H, h = t - e * H;
    int dst = (e < EE) ? ei[EE + e] : (e - EE);
    float v = expf(g_ebuf[t] - g_nmax[dst * H + h]);
    g_ebuf[t] = v;
    atomicAdd(&g_nsum[dst * H + h], v);
}

// ------------- edge pass 3 (layers 0/1): weighted scatter, one warp per edge ---
__global__ void epass3_l01(const int *__restrict__ ei) {
    int w = (blockIdx.x * blockDim.x + threadIdx.x) >> 5;
    int lane = threadIdx.x & 31;
    if (w >= ET) return;
    int src, dst;
    if (w < EE) { src = ei[w]; dst = ei[EE + w]; } else { src = dst = w - EE; }
    int h = lane >> 3;                        // 4 heads x 32 ch; lane*4 cols
    float coef = g_ebuf[w * 4 + h] / g_nsum[dst * 4 + h];
    float4 v = *(const float4 *)(g_xw + src * 128 + lane * 4);
    red_add_v4(g_acc + dst * 128 + lane * 4,
               v.x * coef, v.y * coef, v.z * coef, v.w * coef);
}

// ------------- edge pass 3 (layer 2): 12 floats per edge, one thread per edge --
__global__ void epass3_l2(const int *__restrict__ ei) {
    int e = blockIdx.x * blockDim.x + threadIdx.x;
    if (e >= ET) return;
    int src, dst;
    if (e < EE) { src = ei[e]; dst = ei[EE + e]; } else { src = dst = e - EE; }
    float c[6];
#pragma unroll
    for (int h = 0; h < 6; h++) c[h] = g_ebuf[e * 6 + h] / g_nsum[dst * 6 + h];
    const float *xp = g_xw + src * 12;
    float *p = g_acc + dst * 12;
    float v[12];
#pragma unroll
    for (int i = 0; i < 12; i++) v[i] = xp[i] * c[i >> 1];
    red_add_v4(p + 0, v[0], v[1], v[2],  v[3]);
    red_add_v4(p + 4, v[4], v[5], v[6],  v[7]);
    red_add_v4(p + 8, v[8], v[9], v[10], v[11]);
}

// ------------- finalize layers 0/1: relu(acc + biases) -> g_h ------------------
__global__ void finalize01(const float *__restrict__ cb, const float *__restrict__ lb) {
    int t = blockIdx.x * blockDim.x + threadIdx.x;
    if (t >= NN * 128) return;
    int c = t & 127;
    float v = g_acc[t] + cb[c] + lb[c];
    g_h[t] = v > 0.f ? v : 0.f;
}

// ------------- layer2 small GEMM: g_xw[N,12] = h@c2_W ; g_lin2[N,2] = h@l2_W ---
__global__ __launch_bounds__(256) void gemm_l2(const float *__restrict__ c2W,
                                               const float *__restrict__ l2W) {
    __shared__ float Ah[64][128];
    __shared__ float Ws[128 * 14];
    int tid = threadIdx.x;
    int n0 = blockIdx.x * 64;
    for (int i = tid; i < 128 * 12; i += 256) Ws[(i / 12) * 14 + (i % 12)] = c2W[i];
    for (int i = tid; i < 128 * 2;  i += 256) Ws[(i / 2) * 14 + 12 + (i % 2)] = l2W[i];
#pragma unroll
    for (int t = 0; t < 8; t++) {
        int idx = tid + t * 256;          // 0..2047 float4s
        int r = idx >> 5, q = idx & 31;
        int n = n0 + r;
        float4 v = make_float4(0.f, 0.f, 0.f, 0.f);
        if (n < NN) v = *(const float4 *)(g_h + n * 128 + q * 4);
        *((float4 *)&Ah[r][q * 4]) = v;
    }
    __syncthreads();
    for (int o = tid; o < 64 * 14; o += 256) {
        int r = o / 14, col = o - r * 14;
        int n = n0 + r;
        if (n >= NN) continue;
        float s = 0.f;
#pragma unroll
        for (int k = 0; k < 128; k++) s += Ah[r][k] * Ws[k * 14 + col];
        if (col < 12) g_xw[n * 12 + col] = s;
        else          g_lin2[n * 2 + (col - 12)] = s;
    }
}

// ------------- finalize layer2: mean over heads + linear + biases --------------
__global__ void finalize2(const float *__restrict__ cb, const float *__restrict__ lb,
                          float *__restrict__ out) {
    int t = blockIdx.x * blockDim.x + threadIdx.x;
    if (t >= NN * 2) return;
    int n = t >> 1, o = t & 1;
    float s = 0.f;
#pragma unroll
    for (int h = 0; h < 6; h++) s += g_acc[n * 12 + h * 2 + o];
    out[t] = s * (1.f / 6.f) + cb[o] + g_lin2[t] + lb[o];
}

// ---------------- launch --------------------------------------------------------
extern "C" void kernel_launch(void *const *d_in, const int *in_sizes, int n_in,
                              void *d_out, int out_size) {
    const float *x   = (const float *)d_in[0];
    const int   *ei  = (const int *)d_in[1];
    // d_in[2] edge_attr: ignored (GATConv edge_dim=None)
    const float *c0W = (const float *)d_in[3],  *c0as = (const float *)d_in[4];
    const float *c0ad= (const float *)d_in[5],  *c0b  = (const float *)d_in[6];
    const float *l0W = (const float *)d_in[7],  *l0b  = (const float *)d_in[8];
    const float *c1W = (const float *)d_in[9],  *c1as = (const float *)d_in[10];
    const float *c1ad= (const float *)d_in[11], *c1b  = (const float *)d_in[12];
    const float *l1W = (const float *)d_in[13], *l1b  = (const float *)d_in[14];
    const float *c2W = (const float *)d_in[15], *c2as = (const float *)d_in[16];
    const float *c2ad= (const float *)d_in[17], *c2b  = (const float *)d_in[18];
    const float *l2W = (const float *)d_in[19], *l2b  = (const float *)d_in[20];
    float *out = (float *)d_out;

    dim3 gg((NN + 127) / 128, 2);
    int gE4  = (ET * 4 + 255) / 256;
    int gE6  = (ET * 6 + 255) / 256;
    int gE32 = (ET + 7) / 8;                 // one warp per edge, 8 warps/block
    int gN4  = (NN * 4 + 255) / 256;
    int gN6  = (NN * 6 + 255) / 256;
    int gNF  = (NN * 128) / 256;
    int gE1  = (ET + 255) / 256;
    int gN2  = (NN * 2 + 255) / 256;

    // ---- layer 0 ----
    gemm_dual<<<gg, 256>>>(x, c0W, l0W, 1);
    logits01<<<gN4, 256>>>(c0as, c0ad);
    epass1<4><<<gE4, 256>>>(ei);
    epass2<4><<<gE4, 256>>>(ei);
    epass3_l01<<<gE32, 256>>>(ei);
    finalize01<<<gNF, 256>>>(c0b, l0b);

    // ---- layer 1 ----
    gemm_dual<<<gg, 256>>>(x, c1W, l1W, 0);
    logits01<<<gN4, 256>>>(c1as, c1ad);
    epass1<4><<<gE4, 256>>>(ei);
    epass2<4><<<gE4, 256>>>(ei);
    epass3_l01<<<gE32, 256>>>(ei);
    finalize01<<<gNF, 256>>>(c1b, l1b);

    // ---- layer 2 ----
    gemm_l2<<<(NN + 63) / 64, 256>>>(c2W, l2W);
    logits2<<<gN6, 256>>>(c2as, c2ad);
    epass1<6><<<gE6, 256>>>(ei);
    epass2<6><<<gE6, 256>>>(ei);
    epass3_l2<<<gE1, 256>>>(ei);
    finalize2<<<gN2, 256>>>(c2b, l2b, out);
}

// round 3
// speedup vs baseline: 1.2973x; 1.2973x over previous
#include <cuda_runtime.h>
#include <math.h>

#define NN 50000
#define EE 800000
#define ET 850000        // EE + NN self loops
#define FNEG 0.2f

// ---------------- static device scratch (no allocation allowed) ----------------
__device__ float g_xw [NN * 128];    // per-layer x@W (layer2: [N,12])
__device__ float g_acc[NN * 128];    // linear part (layer2: unused)
__device__ float g_h  [NN * 128];    // activations between layers
__device__ float g_als[NN * 6];
__device__ float g_ald[NN * 6];
__device__ float g_ebuf[5100000];    // ET * 6 edge alpha / exp values
__device__ float g_lin2[NN * 2];     // layer2 linear part
// CSR by destination
__device__ int g_cnt[NN];
__device__ int g_rowptr[NN + 1];
__device__ int g_woff[NN];
__device__ int g_csrc[ET];

// ---------------- helpers ----------------
__device__ __forceinline__ unsigned long long pk2(float x, float y) {
    unsigned long long r;
    asm("mov.b64 %0, {%1, %2};" : "=l"(r) : "f"(x), "f"(y));
    return r;
}
__device__ __forceinline__ void upk2(unsigned long long v, float &x, float &y) {
    asm("mov.b64 {%0, %1}, %2;" : "=f"(x), "=f"(y) : "l"(v));
}

// ================= CSR build (counting sort by dst) ============================
__global__ void csr_zero() {
    int t = blockIdx.x * blockDim.x + threadIdx.x;
    if (t < NN) g_cnt[t] = 0;
}
__global__ void csr_hist(const int *__restrict__ ei) {
    int e = blockIdx.x * blockDim.x + threadIdx.x;
    if (e >= ET) return;
    int dst = (e < EE) ? ei[EE + e] : (e - EE);
    atomicAdd(&g_cnt[dst], 1);
}
__global__ __launch_bounds__(1024) void csr_scan() {
    __shared__ int partial[1024];
    const int CH = (NN + 1023) / 1024;   // 49
    int t = threadIdx.x;
    int start = t * CH;
    int s = 0;
#pragma unroll 7
    for (int i = 0; i < CH; i++) {
        int idx = start + i;
        if (idx < NN) s += g_cnt[idx];
    }
    partial[t] = s;
    __syncthreads();
    // Hillis-Steele inclusive scan
    for (int off = 1; off < 1024; off <<= 1) {
        int u = (t >= off) ? partial[t - off] : 0;
        __syncthreads();
        partial[t] += u;
        __syncthreads();
    }
    int run = partial[t] - s;            // exclusive prefix
    for (int i = 0; i < CH; i++) {
        int idx = start + i;
        if (idx < NN) {
            g_rowptr[idx] = run;
            g_woff[idx] = run;
            run += g_cnt[idx];
        }
    }
    if (t == 0) g_rowptr[NN] = ET;
}
__global__ void csr_scatter(const int *__restrict__ ei) {
    int e = blockIdx.x * blockDim.x + threadIdx.x;
    if (e >= ET) return;
    int src, dst;
    if (e < EE) { src = ei[e]; dst = ei[EE + e]; } else { src = dst = e - EE; }
    int pos = atomicAdd(&g_woff[dst], 1);
    g_csrc[pos] = src;
}

// ---------------- dense GEMM: C[N,128] = A[N,128] @ B[128,128] -----------------
__global__ __launch_bounds__(256) void gemm_dual(const float *__restrict__ Ain,
                                                 const float *__restrict__ B0,
                                                 const float *__restrict__ B1,
                                                 int srcX) {
    const float *A = srcX ? Ain : g_h;
    const float *B = (blockIdx.y == 0) ? B0 : B1;
    float *C       = (blockIdx.y == 0) ? g_xw : g_acc;

    __shared__ float As[16][128];
    __shared__ float Bs[16][128];

    int tid = threadIdx.x;
    int tr = tid >> 4, tc = tid & 15;
    int rowBase = blockIdx.x * 128;

    unsigned long long acc[8][4];
#pragma unroll
    for (int i = 0; i < 8; i++)
#pragma unroll
        for (int j = 0; j < 4; j++) acc[i][j] = 0ULL;

    for (int k0 = 0; k0 < 128; k0 += 16) {
#pragma unroll
        for (int t = 0; t < 2; t++) {
            int idx = tid + t * 256;
            int r = idx >> 2, kq = idx & 3;
            int grow = rowBase + r;
            float4 v = make_float4(0.f, 0.f, 0.f, 0.f);
            if (grow < NN) v = *(const float4 *)(A + grow * 128 + k0 + kq * 4);
            As[kq * 4 + 0][r] = v.x;
            As[kq * 4 + 1][r] = v.y;
            As[kq * 4 + 2][r] = v.z;
            As[kq * 4 + 3][r] = v.w;
        }
#pragma unroll
        for (int t = 0; t < 2; t++) {
            int idx = tid + t * 256;
            int r = idx >> 5, cq = idx & 31;
            *((float4 *)&Bs[r][cq * 4]) = *(const float4 *)(B + (k0 + r) * 128 + cq * 4);
        }
        __syncthreads();
#pragma unroll
        for (int k = 0; k < 16; k++) {
            float4 a0 = *(const float4 *)&As[k][tr * 8];
            float4 a1 = *(const float4 *)&As[k][tr * 8 + 4];
            float4 b0 = *(const float4 *)&Bs[k][tc * 8];
            float4 b1 = *(const float4 *)&Bs[k][tc * 8 + 4];
            unsigned long long bp[4] = {pk2(b0.x, b0.y), pk2(b0.z, b0.w),
                                        pk2(b1.x, b1.y), pk2(b1.z, b1.w)};
            float av[8] = {a0.x, a0.y, a0.z, a0.w, a1.x, a1.y, a1.z, a1.w};
#pragma unroll
            for (int i = 0; i < 8; i++) {
                unsigned long long ap = pk2(av[i], av[i]);
#pragma unroll
                for (int j = 0; j < 4; j++)
                    asm("fma.rn.f32x2 %0, %1, %2, %0;"
                        : "+l"(acc[i][j]) : "l"(ap), "l"(bp[j]));
            }
        }
        __syncthreads();
    }
#pragma unroll
    for (int i = 0; i < 8; i++) {
        int row = rowBase + tr * 8 + i;
        if (row < NN) {
            float o[8];
#pragma unroll
            for (int j = 0; j < 4; j++) upk2(acc[i][j], o[j * 2], o[j * 2 + 1]);
            *(float4 *)(C + row * 128 + tc * 8)     = make_float4(o[0], o[1], o[2], o[3]);
            *(float4 *)(C + row * 128 + tc * 8 + 4) = make_float4(o[4], o[5], o[6], o[7]);
        }
    }
}

// ------------- per-node attention logits (layers 0/1, H=4, C=32) ---------------
__global__ void logits01(const float *__restrict__ a_s, const float *__restrict__ a_d) {
    int t = blockIdx.x * blockDim.x + threadIdx.x;
    if (t >= NN * 4) return;
    int n = t >> 2, h = t & 3;
    const float *xr = g_xw + n * 128 + h * 32;
    float s = 0.f, d = 0.f;
#pragma unroll
    for (int c = 0; c < 32; c++) {
        float v = xr[c];
        s += v * a_s[h * 32 + c];
        d += v * a_d[h * 32 + c];
    }
    g_als[t] = s;
    g_ald[t] = d;
}

// ------------- layer2 logits (H=6, C=2) ----------------------------------------
__global__ void logits2(const float *__restrict__ a_s, const float *__restrict__ a_d) {
    int t = blockIdx.x * blockDim.x + threadIdx.x;
    if (t >= NN * 6) return;
    int n = t / 6, h = t - n * 6;
    float x0 = g_xw[n * 12 + h * 2], x1 = g_xw[n * 12 + h * 2 + 1];
    g_als[t] = x0 * a_s[h * 2] + x1 * a_s[h * 2 + 1];
    g_ald[t] = x0 * a_d[h * 2] + x1 * a_d[h * 2 + 1];
}

// ============ fused node pass (layers 0/1): softmax + gather + relu ============
// one warp per destination node
__global__ __launch_bounds__(256) void nodepass01(const float *__restrict__ cb,
                                                  const float *__restrict__ lb) {
    int w = (blockIdx.x * blockDim.x + threadIdx.x) >> 5;
    int lane = threadIdx.x & 31;
    if (w >= NN) return;
    int base = g_rowptr[w];
    int deg  = g_rowptr[w + 1] - base;

    // ---- phase 1: alpha + segment max (mapping: e = lane>>2, h = lane&3) ----
    int h4 = lane & 3;
    float ald_h = g_ald[w * 4 + h4];
    float mx = -__int_as_float(0x7F800000) * 0.f - __int_as_float(0x7F800000); // -inf
    mx = __int_as_float(0xFF800000);
    for (int k = lane >> 2; k < deg; k += 8) {
        int src = g_csrc[base + k];
        float a = g_als[src * 4 + h4] + ald_h;
        a = a > 0.f ? a : FNEG * a;
        g_ebuf[(base + k) * 4 + h4] = a;
        mx = fmaxf(mx, a);
    }
    mx = fmaxf(mx, __shfl_xor_sync(0xffffffffu, mx, 4));
    mx = fmaxf(mx, __shfl_xor_sync(0xffffffffu, mx, 8));
    mx = fmaxf(mx, __shfl_xor_sync(0xffffffffu, mx, 16));

    // ---- phase 2: exp + segment sum (reads own writes; no warp fence needed) --
    float sum = 0.f;
    for (int k = lane >> 2; k < deg; k += 8) {
        float a = g_ebuf[(base + k) * 4 + h4];
        float e = __expf(a - mx);
        g_ebuf[(base + k) * 4 + h4] = e;
        sum += e;
    }
    sum += __shfl_xor_sync(0xffffffffu, sum, 4);
    sum += __shfl_xor_sync(0xffffffffu, sum, 8);
    sum += __shfl_xor_sync(0xffffffffu, sum, 16);
    float inv = 1.f / sum;
    __syncwarp();   // phase 3 reads ebuf written by other lanes

    // ---- phase 3: gather xw[src]*coef (mapping: channels lane*4.., head lane>>3)
    int hc = lane >> 3;
    float cinv = __shfl_sync(0xffffffffu, inv, hc);  // lane hc holds h4==hc
    float4 acc = make_float4(0.f, 0.f, 0.f, 0.f);
    int k = 0;
    for (; k + 1 < deg; k += 2) {
        int src0 = g_csrc[base + k];
        int src1 = g_csrc[base + k + 1];
        float e0 = g_ebuf[(base + k) * 4 + hc];
        float e1 = g_ebuf[(base + k + 1) * 4 + hc];
        float4 v0 = *(const float4 *)(g_xw + src0 * 128 + lane * 4);
        float4 v1 = *(const float4 *)(g_xw + src1 * 128 + lane * 4);
        float c0 = e0 * cinv, c1 = e1 * cinv;
        acc.x += c0 * v0.x + c1 * v1.x;
        acc.y += c0 * v0.y + c1 * v1.y;
        acc.z += c0 * v0.z + c1 * v1.z;
        acc.w += c0 * v0.w + c1 * v1.w;
    }
    if (k < deg) {
        int src0 = g_csrc[base + k];
        float e0 = g_ebuf[(base + k) * 4 + hc];
        float4 v0 = *(const float4 *)(g_xw + src0 * 128 + lane * 4);
        float c0 = e0 * cinv;
        acc.x += c0 * v0.x; acc.y += c0 * v0.y;
        acc.z += c0 * v0.z; acc.w += c0 * v0.w;
    }

    // ---- epilogue: + linear part + biases, relu -> g_h ----
    int c = lane * 4;
    float4 lin = *(const float4 *)(g_acc + w * 128 + c);
    float4 b0 = *(const float4 *)(cb + c);
    float4 b1 = *(const float4 *)(lb + c);
    float4 o;
    o.x = acc.x + lin.x + b0.x + b1.x;
    o.y = acc.y + lin.y + b0.y + b1.y;
    o.z = acc.z + lin.z + b0.z + b1.z;
    o.w = acc.w + lin.w + b0.w + b1.w;
    o.x = o.x > 0.f ? o.x : 0.f;
    o.y = o.y > 0.f ? o.y : 0.f;
    o.z = o.z > 0.f ? o.z : 0.f;
    o.w = o.w > 0.f ? o.w : 0.f;
    *(float4 *)(g_h + w * 128 + c) = o;
}

// ============ fused node pass (layer 2, H=6, C=2, concat=False) ================
__global__ __launch_bounds__(256) void nodepass2(const float *__restrict__ cb,
                                                 const float *__restrict__ lb,
                                                 float *__restrict__ out) {
    int w = (blockIdx.x * blockDim.x + threadIdx.x) >> 5;
    int lane = threadIdx.x & 31;
    if (w >= NN) return;
    int base = g_rowptr[w];
    int deg  = g_rowptr[w + 1] - base;

    // phase 1/2 mapping: e = lane>>3 (4 edges/iter), h = lane&7 (heads 0..5 active)
    int h8 = lane & 7;
    bool hact = h8 < 6;
    float ald_h = hact ? g_ald[w * 6 + h8] : 0.f;
    float mx = __int_as_float(0xFF800000);
    for (int k = lane >> 3; k < deg; k += 4) {
        int src = g_csrc[base + k];
        if (hact) {
            float a = g_als[src * 6 + h8] + ald_h;
            a = a > 0.f ? a : FNEG * a;
            g_ebuf[(base + k) * 6 + h8] = a;
            mx = fmaxf(mx, a);
        }
    }
    mx = fmaxf(mx, __shfl_xor_sync(0xffffffffu, mx, 8));
    mx = fmaxf(mx, __shfl_xor_sync(0xffffffffu, mx, 16));
    float sum = 0.f;
    for (int k = lane >> 3; k < deg; k += 4) {
        if (hact) {
            float a = g_ebuf[(base + k) * 6 + h8];
            float e = __expf(a - mx);
            g_ebuf[(base + k) * 6 + h8] = e;
            sum += e;
        }
    }
    sum += __shfl_xor_sync(0xffffffffu, sum, 8);
    sum += __shfl_xor_sync(0xffffffffu, sum, 16);
    float inv = (hact && sum != 0.f) ? 1.f / sum : 0.f;
    __syncwarp();

    // phase 3: lanes 0..11 -> (head = lane>>1, out-col = lane&1)
    float cinv = __shfl_sync(0xffffffffu, inv, lane >> 1);
    float acc = 0.f;
    bool act = lane < 12;
    for (int k = 0; k < deg; k++) {
        int src = g_csrc[base + k];
        if (act) {
            float ee = g_ebuf[(base + k) * 6 + (lane >> 1)];
            float v  = g_xw[src * 12 + lane];
            acc += ee * cinv * v;
        }
    }
    // mean over 6 heads: sum lanes {o, o+2, ..., o+10} into lanes 0/1
    float s = acc;
    s += __shfl_down_sync(0xffffffffu, s, 2);
    s += __shfl_down_sync(0xffffffffu, s, 4);
    s += __shfl_down_sync(0xffffffffu, s, 8);
    if (lane < 2)
        out[w * 2 + lane] = s * (1.f / 6.f) + cb[lane] + g_lin2[w * 2 + lane] + lb[lane];
}

// ------------- layer2 small GEMM: g_xw[N,12] = h@c2_W ; g_lin2[N,2] = h@l2_W ---
__global__ __launch_bounds__(256) void gemm_l2(const float *__restrict__ c2W,
                                               const float *__restrict__ l2W) {
    __shared__ float Ah[64][128];
    __shared__ float Ws[128 * 14];
    int tid = threadIdx.x;
    int n0 = blockIdx.x * 64;
    for (int i = tid; i < 128 * 12; i += 256) Ws[(i / 12) * 14 + (i % 12)] = c2W[i];
    for (int i = tid; i < 128 * 2;  i += 256) Ws[(i / 2) * 14 + 12 + (i % 2)] = l2W[i];
#pragma unroll
    for (int t = 0; t < 8; t++) {
        int idx = tid + t * 256;
        int r = idx >> 5, q = idx & 31;
        int n = n0 + r;
        float4 v = make_float4(0.f, 0.f, 0.f, 0.f);
        if (n < NN) v = *(const float4 *)(g_h + n * 128 + q * 4);
        *((float4 *)&Ah[r][q * 4]) = v;
    }
    __syncthreads();
    for (int o = tid; o < 64 * 14; o += 256) {
        int r = o / 14, col = o - r * 14;
        int n = n0 + r;
        if (n >= NN) continue;
        float s = 0.f;
#pragma unroll
        for (int k = 0; k < 128; k++) s += Ah[r][k] * Ws[k * 14 + col];
        if (col < 12) g_xw[n * 12 + col] = s;
        else          g_lin2[n * 2 + (col - 12)] = s;
    }
}

// ---------------- launch --------------------------------------------------------
extern "C" void kernel_launch(void *const *d_in, const int *in_sizes, int n_in,
                              void *d_out, int out_size) {
    const float *x   = (const float *)d_in[0];
    const int   *ei  = (const int *)d_in[1];
    // d_in[2] edge_attr: ignored (GATConv edge_dim=None)
    const float *c0W = (const float *)d_in[3],  *c0as = (const float *)d_in[4];
    const float *c0ad= (const float *)d_in[5],  *c0b  = (const float *)d_in[6];
    const float *l0W = (const float *)d_in[7],  *l0b  = (const float *)d_in[8];
    const float *c1W = (const float *)d_in[9],  *c1as = (const float *)d_in[10];
    const float *c1ad= (const float *)d_in[11], *c1b  = (const float *)d_in[12];
    const float *l1W = (const float *)d_in[13], *l1b  = (const float *)d_in[14];
    const float *c2W = (const float *)d_in[15], *c2as = (const float *)d_in[16];
    const float *c2ad= (const float *)d_in[17], *c2b  = (const float *)d_in[18];
    const float *l2W = (const float *)d_in[19], *l2b  = (const float *)d_in[20];
    float *out = (float *)d_out;

    dim3 gg((NN + 127) / 128, 2);
    int gN4 = (NN * 4 + 255) / 256;
    int gN6 = (NN * 6 + 255) / 256;
    int gE1 = (ET + 255) / 256;
    int gNW = (NN * 32 + 255) / 256;   // one warp per node

    // ---- CSR build (edge structure is shared by all layers) ----
    csr_zero<<<(NN + 255) / 256, 256>>>();
    csr_hist<<<gE1, 256>>>(ei);
    csr_scan<<<1, 1024>>>();
    csr_scatter<<<gE1, 256>>>(ei);

    // ---- layer 0 ----
    gemm_dual<<<gg, 256>>>(x, c0W, l0W, 1);
    logits01<<<gN4, 256>>>(c0as, c0ad);
    nodepass01<<<gNW, 256>>>(c0b, l0b);

    // ---- layer 1 ----
    gemm_dual<<<gg, 256>>>(x, c1W, l1W, 0);
    logits01<<<gN4, 256>>>(c1as, c1ad);
    nodepass01<<<gNW, 256>>>(c1b, l1b);

    // ---- layer 2 ----
    gemm_l2<<<(NN + 63) / 64, 256>>>(c2W, l2W);
    logits2<<<gN6, 256>>>(c2as, c2ad);
    nodepass2<<<gNW, 256>>>(c2b, l2b, out);
}

// round 7
// speedup vs baseline: 1.4970x; 1.1539x over previous
#include <cuda_runtime.h>
#include <math.h>
#include <cstdint>

#define NN 50000
#define EE 800000
#define ET 850000        // EE + NN self loops
#define FNEG 0.2f

// ---------------- static device scratch (no allocation allowed) ----------------
__device__ float g_xw [NN * 128];    // per-layer x@W (layer2: [N,12])
__device__ float g_acc[NN * 128];    // linear part
__device__ float g_h  [NN * 128];    // activations between layers
__device__ float g_als[NN * 6];
__device__ float g_ald[NN * 6];
__device__ float g_ebuf[5100000];    // ET * 6 edge exp values
__device__ float g_lin2[NN * 2];     // layer2 linear part
// CSR by destination
__device__ int g_cnt[NN];
__device__ int g_rowptr[NN + 1];
__device__ int g_woff[NN];
__device__ int g_csrc[ET];

// ---------------- helpers ----------------
__device__ __forceinline__ unsigned long long pk2(float x, float y) {
    unsigned long long r;
    asm("mov.b64 %0, {%1, %2};" : "=l"(r) : "f"(x), "f"(y));
    return r;
}
__device__ __forceinline__ void upk2(unsigned long long v, float &x, float &y) {
    asm("mov.b64 {%0, %1}, %2;" : "=f"(x), "=f"(y) : "l"(v));
}

// ================= CSR build (counting sort by dst) ============================
__global__ void csr_zero() {
    int t = blockIdx.x * blockDim.x + threadIdx.x;
    if (t < NN) g_cnt[t] = 0;
}
__global__ void csr_hist(const int *__restrict__ ei) {
    int e0 = (blockIdx.x * blockDim.x + threadIdx.x) * 4;
#pragma unroll
    for (int u = 0; u < 4; u++) {
        int e = e0 + u;
        if (e < ET) {
            int dst = (e < EE) ? ei[EE + e] : (e - EE);
            atomicAdd(&g_cnt[dst], 1);
        }
    }
}
__global__ __launch_bounds__(1024) void csr_scan() {
    __shared__ int partial[1024];
    const int CH = (NN + 1023) / 1024;
    int t = threadIdx.x;
    int start = t * CH;
    int s = 0;
#pragma unroll 7
    for (int i = 0; i < CH; i++) {
        int idx = start + i;
        if (idx < NN) s += g_cnt[idx];
    }
    partial[t] = s;
    __syncthreads();
    for (int off = 1; off < 1024; off <<= 1) {
        int u = (t >= off) ? partial[t - off] : 0;
        __syncthreads();
        partial[t] += u;
        __syncthreads();
    }
    int run = partial[t] - s;
    for (int i = 0; i < CH; i++) {
        int idx = start + i;
        if (idx < NN) {
            g_rowptr[idx] = run;
            g_woff[idx] = run;
            run += g_cnt[idx];
        }
    }
    if (t == 0) g_rowptr[NN] = ET;
}
__global__ void csr_scatter(const int *__restrict__ ei) {
    int e0 = (blockIdx.x * blockDim.x + threadIdx.x) * 4;
    int srcv[4], dstv[4];
#pragma unroll
    for (int u = 0; u < 4; u++) {
        int e = e0 + u;
        if (e < ET) {
            if (e < EE) { srcv[u] = ei[e]; dstv[u] = ei[EE + e]; }
            else        { srcv[u] = dstv[u] = e - EE; }
        } else dstv[u] = -1;
    }
    int pos[4];
#pragma unroll
    for (int u = 0; u < 4; u++)
        if (dstv[u] >= 0) pos[u] = atomicAdd(&g_woff[dstv[u]], 1);
#pragma unroll
    for (int u = 0; u < 4; u++)
        if (dstv[u] >= 0) g_csrc[pos[u]] = srcv[u];
}

// ======= dense GEMM: C[N,128] = A[N,128] @ B[128,128]  (+fused logits) =========
// blockIdx.y == 0: B=B0, C=g_xw, epilogue computes g_als/g_ald
// blockIdx.y == 1: B=B1, C=g_acc
__global__ __launch_bounds__(256) void gemm_dual(const float *__restrict__ Ain,
                                                 const float *__restrict__ B0,
                                                 const float *__restrict__ B1,
                                                 int srcX,
                                                 const float *__restrict__ a_s,
                                                 const float *__restrict__ a_d) {
    const float *A = srcX ? Ain : g_h;
    const float *B = (blockIdx.y == 0) ? B0 : B1;
    float *C       = (blockIdx.y == 0) ? g_xw : g_acc;

    __shared__ float As[16][128];   // [k][row]
    __shared__ float Bs[16][128];   // [k][col]

    int tid = threadIdx.x;
    int tr = tid >> 4, tc = tid & 15;
    int rowBase = blockIdx.x * 128;

    unsigned long long acc[8][4];
#pragma unroll
    for (int i = 0; i < 8; i++)
#pragma unroll
        for (int j = 0; j < 4; j++) acc[i][j] = 0ULL;

    for (int k0 = 0; k0 < 128; k0 += 16) {
#pragma unroll
        for (int t = 0; t < 2; t++) {
            int idx = tid + t * 256;
            int r = idx >> 2, kq = idx & 3;
            int grow = rowBase + r;
            float4 v = make_float4(0.f, 0.f, 0.f, 0.f);
            if (grow < NN) v = *(const float4 *)(A + grow * 128 + k0 + kq * 4);
            As[kq * 4 + 0][r] = v.x;
            As[kq * 4 + 1][r] = v.y;
            As[kq * 4 + 2][r] = v.z;
            As[kq * 4 + 3][r] = v.w;
        }
#pragma unroll
        for (int t = 0; t < 2; t++) {
            int idx = tid + t * 256;
            int r = idx >> 5, cq = idx & 31;
            *((float4 *)&Bs[r][cq * 4]) = *(const float4 *)(B + (k0 + r) * 128 + cq * 4);
        }
        __syncthreads();
#pragma unroll
        for (int k = 0; k < 16; k++) {
            float4 a0 = *(const float4 *)&As[k][tr * 8];
            float4 a1 = *(const float4 *)&As[k][tr * 8 + 4];
            // b pairs loaded directly as 64-bit from shared (no packing)
            const unsigned long long *bpp = (const unsigned long long *)&Bs[k][tc * 8];
            unsigned long long bp0 = bpp[0], bp1 = bpp[1], bp2 = bpp[2], bp3 = bpp[3];
            float av[8] = {a0.x, a0.y, a0.z, a0.w, a1.x, a1.y, a1.z, a1.w};
#pragma unroll
            for (int i = 0; i < 8; i++) {
                unsigned long long ap = pk2(av[i], av[i]);
                asm("fma.rn.f32x2 %0, %1, %2, %0;" : "+l"(acc[i][0]) : "l"(ap), "l"(bp0));
                asm("fma.rn.f32x2 %0, %1, %2, %0;" : "+l"(acc[i][1]) : "l"(ap), "l"(bp1));
                asm("fma.rn.f32x2 %0, %1, %2, %0;" : "+l"(acc[i][2]) : "l"(ap), "l"(bp2));
                asm("fma.rn.f32x2 %0, %1, %2, %0;" : "+l"(acc[i][3]) : "l"(ap), "l"(bp3));
            }
        }
        __syncthreads();
    }

    bool doLog = (blockIdx.y == 0);
    int h = tc >> 2, qo = (tc & 3) * 8;
    float asub[8], dsub[8];
    if (doLog) {
#pragma unroll
        for (int q = 0; q < 8; q++) {
            asub[q] = a_s[h * 32 + qo + q];
            dsub[q] = a_d[h * 32 + qo + q];
        }
    }
#pragma unroll
    for (int i = 0; i < 8; i++) {
        int row = rowBase + tr * 8 + i;
        float o[8];
#pragma unroll
        for (int j = 0; j < 4; j++) upk2(acc[i][j], o[j * 2], o[j * 2 + 1]);
        if (row < NN) {
            *(float4 *)(C + row * 128 + tc * 8)     = make_float4(o[0], o[1], o[2], o[3]);
            *(float4 *)(C + row * 128 + tc * 8 + 4) = make_float4(o[4], o[5], o[6], o[7]);
        }
        if (doLog) {
            float ps = 0.f, pd = 0.f;
#pragma unroll
            for (int q = 0; q < 8; q++) {
                ps += o[q] * asub[q];
                pd += o[q] * dsub[q];
            }
            ps += __shfl_xor_sync(0xffffffffu, ps, 1);
            ps += __shfl_xor_sync(0xffffffffu, ps, 2);
            pd += __shfl_xor_sync(0xffffffffu, pd, 1);
            pd += __shfl_xor_sync(0xffffffffu, pd, 2);
            if ((tc & 3) == 0 && row < NN) {
                g_als[row * 4 + h] = ps;
                g_ald[row * 4 + h] = pd;
            }
        }
    }
}

// ------------- layer2 logits (H=6, C=2) ----------------------------------------
__global__ void logits2(const float *__restrict__ a_s, const float *__restrict__ a_d) {
    int t = blockIdx.x * blockDim.x + threadIdx.x;
    if (t >= NN * 6) return;
    int n = t / 6, h = t - n * 6;
    float x0 = g_xw[n * 12 + h * 2], x1 = g_xw[n * 12 + h * 2 + 1];
    g_als[t] = x0 * a_s[h * 2] + x1 * a_s[h * 2 + 1];
    g_ald[t] = x0 * a_d[h * 2] + x1 * a_d[h * 2 + 1];
}

// ============ fused node pass (layers 0/1): softmax + gather + relu ============
__global__ __launch_bounds__(256) void nodepass01(const float *__restrict__ cb,
                                                  const float *__restrict__ lb) {
    int w = (blockIdx.x * blockDim.x + threadIdx.x) >> 5;
    int lane = threadIdx.x & 31;
    if (w >= NN) return;
    int base = g_rowptr[w];
    int deg  = g_rowptr[w + 1] - base;

    int h4 = lane & 3;
    float ald_h = g_ald[w * 4 + h4];
    float mx = __int_as_float(0xFF800000);
    float sum = 0.f;

    if (deg <= 64) {
        // register-cached alpha path (each lane handles <= 8 edges)
        float areg[8];
        int i = 0;
        for (int k = lane >> 2; k < deg; k += 8, i++) {
            int src = g_csrc[base + k];
            float a = g_als[src * 4 + h4] + ald_h;
            a = a > 0.f ? a : FNEG * a;
            areg[i] = a;
            mx = fmaxf(mx, a);
        }
        mx = fmaxf(mx, __shfl_xor_sync(0xffffffffu, mx, 4));
        mx = fmaxf(mx, __shfl_xor_sync(0xffffffffu, mx, 8));
        mx = fmaxf(mx, __shfl_xor_sync(0xffffffffu, mx, 16));
        i = 0;
        for (int k = lane >> 2; k < deg; k += 8, i++) {
            float e = __expf(areg[i] - mx);
            g_ebuf[(base + k) * 4 + h4] = e;
            sum += e;
        }
    } else {
        for (int k = lane >> 2; k < deg; k += 8) {
            int src = g_csrc[base + k];
            float a = g_als[src * 4 + h4] + ald_h;
            a = a > 0.f ? a : FNEG * a;
            g_ebuf[(base + k) * 4 + h4] = a;
            mx = fmaxf(mx, a);
        }
        mx = fmaxf(mx, __shfl_xor_sync(0xffffffffu, mx, 4));
        mx = fmaxf(mx, __shfl_xor_sync(0xffffffffu, mx, 8));
        mx = fmaxf(mx, __shfl_xor_sync(0xffffffffu, mx, 16));
        for (int k = lane >> 2; k < deg; k += 8) {
            float a = g_ebuf[(base + k) * 4 + h4];
            float e = __expf(a - mx);
            g_ebuf[(base + k) * 4 + h4] = e;
            sum += e;
        }
    }
    sum += __shfl_xor_sync(0xffffffffu, sum, 4);
    sum += __shfl_xor_sync(0xffffffffu, sum, 8);
    sum += __shfl_xor_sync(0xffffffffu, sum, 16);
    float inv = 1.f / sum;
    __syncwarp();   // phase 3 reads ebuf written by other lanes

    // ---- phase 3: gather xw[src]*coef; head = lane>>3, channels lane*4.. ----
    int hc = lane >> 3;
    float cinv = __shfl_sync(0xffffffffu, inv, hc);
    float4 acc = make_float4(0.f, 0.f, 0.f, 0.f);
    int k = 0;
    for (; k + 3 < deg; k += 4) {
        int s0 = g_csrc[base + k],     s1 = g_csrc[base + k + 1];
        int s2 = g_csrc[base + k + 2], s3 = g_csrc[base + k + 3];
        float e0 = g_ebuf[(base + k) * 4 + hc];
        float e1 = g_ebuf[(base + k + 1) * 4 + hc];
        float e2 = g_ebuf[(base + k + 2) * 4 + hc];
        float e3 = g_ebuf[(base + k + 3) * 4 + hc];
        float4 v0 = *(const float4 *)(g_xw + s0 * 128 + lane * 4);
        float4 v1 = *(const float4 *)(g_xw + s1 * 128 + lane * 4);
        float4 v2 = *(const float4 *)(g_xw + s2 * 128 + lane * 4);
        float4 v3 = *(const float4 *)(g_xw + s3 * 128 + lane * 4);
        float c0 = e0 * cinv, c1 = e1 * cinv, c2 = e2 * cinv, c3 = e3 * cinv;
        acc.x += c0 * v0.x + c1 * v1.x + c2 * v2.x + c3 * v3.x;
        acc.y += c0 * v0.y + c1 * v1.y + c2 * v2.y + c3 * v3.y;
        acc.z += c0 * v0.z + c1 * v1.z + c2 * v2.z + c3 * v3.z;
        acc.w += c0 * v0.w + c1 * v1.w + c2 * v2.w + c3 * v3.w;
    }
    for (; k < deg; k++) {
        int s0 = g_csrc[base + k];
        float e0 = g_ebuf[(base + k) * 4 + hc];
        float4 v0 = *(const float4 *)(g_xw + s0 * 128 + lane * 4);
        float c0 = e0 * cinv;
        acc.x += c0 * v0.x; acc.y += c0 * v0.y;
        acc.z += c0 * v0.z; acc.w += c0 * v0.w;
    }

    int c = lane * 4;
    float4 lin = *(const float4 *)(g_acc + w * 128 + c);
    float4 b0 = *(const float4 *)(cb + c);
    float4 b1 = *(const float4 *)(lb + c);
    float4 o;
    o.x = acc.x + lin.x + b0.x + b1.x;
    o.y = acc.y + lin.y + b0.y + b1.y;
    o.z = acc.z + lin.z + b0.z + b1.z;
    o.w = acc.w + lin.w + b0.w + b1.w;
    o.x = o.x > 0.f ? o.x : 0.f;
    o.y = o.y > 0.f ? o.y : 0.f;
    o.z = o.z > 0.f ? o.z : 0.f;
    o.w = o.w > 0.f ? o.w : 0.f;
    *(float4 *)(g_h + w * 128 + c) = o;
}

// ============ fused node pass (layer 2, H=6, C=2, concat=False) ================
__global__ __launch_bounds__(256) void nodepass2(const float *__restrict__ cb,
                                                 const float *__restrict__ lb,
                                                 float *__restrict__ out) {
    int w = (blockIdx.x * blockDim.x + threadIdx.x) >> 5;
    int lane = threadIdx.x & 31;
    if (w >= NN) return;
    int base = g_rowptr[w];
    int deg  = g_rowptr[w + 1] - base;

    int h8 = lane & 7;
    bool hact = h8 < 6;
    float ald_h = hact ? g_ald[w * 6 + h8] : 0.f;
    float mx = __int_as_float(0xFF800000);
    for (int k = lane >> 3; k < deg; k += 4) {
        int src = g_csrc[base + k];
        if (hact) {
            float a = g_als[src * 6 + h8] + ald_h;
            a = a > 0.f ? a : FNEG * a;
            g_ebuf[(base + k) * 6 + h8] = a;
            mx = fmaxf(mx, a);
        }
    }
    mx = fmaxf(mx, __shfl_xor_sync(0xffffffffu, mx, 8));
    mx = fmaxf(mx, __shfl_xor_sync(0xffffffffu, mx, 16));
    float sum = 0.f;
    for (int k = lane >> 3; k < deg; k += 4) {
        if (hact) {
            float a = g_ebuf[(base + k) * 6 + h8];
            float e = __expf(a - mx);
            g_ebuf[(base + k) * 6 + h8] = e;
            sum += e;
        }
    }
    sum += __shfl_xor_sync(0xffffffffu, sum, 8);
    sum += __shfl_xor_sync(0xffffffffu, sum, 16);
    float inv = (hact && sum != 0.f) ? 1.f / sum : 0.f;
    __syncwarp();

    float cinv = __shfl_sync(0xffffffffu, inv, lane >> 1);
    float acc = 0.f;
    bool act = lane < 12;
    for (int k = 0; k < deg; k++) {
        int src = g_csrc[base + k];
        if (act) {
            float ee = g_ebuf[(base + k) * 6 + (lane >> 1)];
            float v  = g_xw[src * 12 + lane];
            acc += ee * cinv * v;
        }
    }
    float s = acc;
    s += __shfl_down_sync(0xffffffffu, s, 2);
    s += __shfl_down_sync(0xffffffffu, s, 4);
    s += __shfl_down_sync(0xffffffffu, s, 8);
    if (lane < 2)
        out[w * 2 + lane] = s * (1.f / 6.f) + cb[lane] + g_lin2[w * 2 + lane] + lb[lane];
}

// ------------- layer2 small GEMM: g_xw[N,12] = h@c2_W ; g_lin2[N,2] = h@l2_W ---
__global__ __launch_bounds__(256) void gemm_l2(const float *__restrict__ c2W,
                                               const float *__restrict__ l2W) {
    __shared__ float Ah[64][128];
    __shared__ float Ws[128 * 14];
    int tid = threadIdx.x;
    int n0 = blockIdx.x * 64;
    for (int i = tid; i < 128 * 12; i += 256) Ws[(i / 12) * 14 + (i % 12)] = c2W[i];
    for (int i = tid; i < 128 * 2;  i += 256) Ws[(i / 2) * 14 + 12 + (i % 2)] = l2W[i];
#pragma unroll
    for (int t = 0; t < 8; t++) {
        int idx = tid + t * 256;
        int r = idx >> 5, q = idx & 31;
        int n = n0 + r;
        float4 v = make_float4(0.f, 0.f, 0.f, 0.f);
        if (n < NN) v = *(const float4 *)(g_h + n * 128 + q * 4);
        *((float4 *)&Ah[r][q * 4]) = v;
    }
    __syncthreads();
    for (int o = tid; o < 64 * 14; o += 256) {
        int r = o / 14, col = o - r * 14;
        int n = n0 + r;
        if (n >= NN) continue;
        float s = 0.f;
#pragma unroll
        for (int k = 0; k < 128; k++) s += Ah[r][k] * Ws[k * 14 + col];
        if (col < 12) g_xw[n * 12 + col] = s;
        else          g_lin2[n * 2 + (col - 12)] = s;
    }
}

// ---------------- launch --------------------------------------------------------
extern "C" void kernel_launch(void *const *d_in, const int *in_sizes, int n_in,
                              void *d_out, int out_size) {
    const float *x   = (const float *)d_in[0];
    const int   *ei  = (const int *)d_in[1];
    // d_in[2] edge_attr: ignored (GATConv edge_dim=None)
    const float *c0W = (const float *)d_in[3],  *c0as = (const float *)d_in[4];
    const float *c0ad= (const float *)d_in[5],  *c0b  = (const float *)d_in[6];
    const float *l0W = (const float *)d_in[7],  *l0b  = (const float *)d_in[8];
    const float *c1W = (const float *)d_in[9],  *c1as = (const float *)d_in[10];
    const float *c1ad= (const float *)d_in[11], *c1b  = (const float *)d_in[12];
    const float *l1W = (const float *)d_in[13], *l1b  = (const float *)d_in[14];
    const float *c2W = (const float *)d_in[15], *c2as = (const float *)d_in[16];
    const float *c2ad= (const float *)d_in[17], *c2b  = (const float *)d_in[18];
    const float *l2W = (const float *)d_in[19], *l2b  = (const float *)d_in[20];
    float *out = (float *)d_out;

    dim3 gg((NN + 127) / 128, 2);
    int gN6 = (NN * 6 + 255) / 256;
    int gE4 = (ET + 1023) / 1024;       // 4 edges per thread
    int gNW = (NN * 32 + 255) / 256;    // one warp per node

    // ---- CSR build (edge structure shared by all layers) ----
    csr_zero<<<(NN + 255) / 256, 256>>>();
    csr_hist<<<gE4, 256>>>(ei);
    csr_scan<<<1, 1024>>>();
    csr_scatter<<<gE4, 256>>>(ei);

    // ---- layer 0 ----
    gemm_dual<<<gg, 256>>>(x, c0W, l0W, 1, c0as, c0ad);
    nodepass01<<<gNW, 256>>>(c0b, l0b);

    // ---- layer 1 ----
    gemm_dual<<<gg, 256>>>(x, c1W, l1W, 0, c1as, c1ad);
    nodepass01<<<gNW, 256>>>(c1b, l1b);

    // ---- layer 2 ----
    gemm_l2<<<(NN + 63) / 64, 256>>>(c2W, l2W);
    logits2<<<gN6, 256>>>(c2as, c2ad);
    nodepass2<<<gNW, 256>>>(c2b, l2b, out);
}

// round 11
// speedup vs baseline: 1.8578x; 1.2410x over previous
#include <cuda_runtime.h>
#include <math.h>
#include <cstdint>

#define NN 50000
#define EE 800000
#define ET 850000        // EE + NN self loops
#define FNEG 0.2f

// ---------------- static device scratch (no allocation allowed) ----------------
__device__ float g_xw [NN * 128];    // per-layer x@W (layer2: [N,12])
__device__ float g_acc[NN * 128];    // linear part
__device__ float g_h  [NN * 128];    // activations between layers
__device__ float g_als[NN * 6];
__device__ float g_ald[NN * 6];
__device__ float g_ebuf[5100000];    // ET * 6 edge exp values
__device__ float g_lin2[NN * 2];     // layer2 linear part
// CSR by destination
__device__ int g_cnt[NN];
__device__ int g_rowptr[NN + 1];
__device__ int g_woff[NN];
__device__ int g_csrc[ET];

// ---------------- helpers ----------------
__device__ __forceinline__ uint32_t f2tf(float f) {
    uint32_t r;
    asm("cvt.rna.tf32.f32 %0, %1;" : "=r"(r) : "f"(f));
    return r;
}

// ================= CSR build (counting sort by dst) ============================
__global__ void csr_zero() {
    int t = blockIdx.x * blockDim.x + threadIdx.x;
    if (t < NN) g_cnt[t] = 0;
}
__global__ void csr_hist(const int *__restrict__ ei) {
    int e0 = (blockIdx.x * blockDim.x + threadIdx.x) * 4;
#pragma unroll
    for (int u = 0; u < 4; u++) {
        int e = e0 + u;
        if (e < ET) {
            int dst = (e < EE) ? ei[EE + e] : (e - EE);
            atomicAdd(&g_cnt[dst], 1);
        }
    }
}
__global__ __launch_bounds__(1024) void csr_scan() {
    __shared__ int partial[1024];
    const int CH = (NN + 1023) / 1024;
    int t = threadIdx.x;
    int start = t * CH;
    int s = 0;
#pragma unroll 7
    for (int i = 0; i < CH; i++) {
        int idx = start + i;
        if (idx < NN) s += g_cnt[idx];
    }
    partial[t] = s;
    __syncthreads();
    for (int off = 1; off < 1024; off <<= 1) {
        int u = (t >= off) ? partial[t - off] : 0;
        __syncthreads();
        partial[t] += u;
        __syncthreads();
    }
    int run = partial[t] - s;
    for (int i = 0; i < CH; i++) {
        int idx = start + i;
        if (idx < NN) {
            g_rowptr[idx] = run;
            g_woff[idx] = run;
            run += g_cnt[idx];
        }
    }
    if (t == 0) g_rowptr[NN] = ET;
}
__global__ void csr_scatter(const int *__restrict__ ei) {
    int e0 = (blockIdx.x * blockDim.x + threadIdx.x) * 4;
    int srcv[4], dstv[4];
#pragma unroll
    for (int u = 0; u < 4; u++) {
        int e = e0 + u;
        if (e < ET) {
            if (e < EE) { srcv[u] = ei[e]; dstv[u] = ei[EE + e]; }
            else        { srcv[u] = dstv[u] = e - EE; }
        } else dstv[u] = -1;
    }
    int pos[4];
#pragma unroll
    for (int u = 0; u < 4; u++)
        if (dstv[u] >= 0) pos[u] = atomicAdd(&g_woff[dstv[u]], 1);
#pragma unroll
    for (int u = 0; u < 4; u++)
        if (dstv[u] >= 0) g_csrc[pos[u]] = srcv[u];
}

// ======= tf32 mma.sync GEMM: C[N,128] = A[N,128] @ B[128,128] (+fused logits) ==
// blockIdx.y == 0: B=B0, C=g_xw, epilogue computes g_als/g_ald
// blockIdx.y == 1: B=B1, C=g_acc
// Block: 128x128 tile, 8 warps in 2(m) x 4(n); warp tile 64x32.
__global__ __launch_bounds__(256) void gemm_mma(const float *__restrict__ Ain,
                                                const float *__restrict__ B0,
                                                const float *__restrict__ B1,
                                                int srcX,
                                                const float *__restrict__ a_s,
                                                const float *__restrict__ a_d) {
    const float *A = srcX ? Ain : g_h;
    const float *B = (blockIdx.y == 0) ? B0 : B1;
    float *C       = (blockIdx.y == 0) ? g_xw : g_acc;
    bool doLog     = (blockIdx.y == 0);

    __shared__ uint32_t As[128][20];    // [row][k] pad->20 (conflict-free frag reads)
    __shared__ uint32_t Bs[16][136];    // [k][col] pad->136

    int tid = threadIdx.x, wid = tid >> 5, lane = tid & 31;
    int warp_m = wid >> 2;              // 0..1  -> rows warp_m*64
    int warp_n = wid & 3;               // 0..3  -> cols warp_n*32 (== head)
    int rowBase = blockIdx.x * 128;
    int g4 = lane >> 2, l4 = lane & 3;  // groupID, thread-in-group

    float acc[4][4][4];
#pragma unroll
    for (int mt = 0; mt < 4; mt++)
#pragma unroll
        for (int nt = 0; nt < 4; nt++)
#pragma unroll
            for (int q = 0; q < 4; q++) acc[mt][nt][q] = 0.f;

    for (int k0 = 0; k0 < 128; k0 += 16) {
        // stage A: 128 rows x 16 k
#pragma unroll
        for (int t = 0; t < 2; t++) {
            int idx = tid + t * 256;
            int r = idx >> 2, kq = idx & 3;
            int grow = rowBase + r;
            float4 v = make_float4(0.f, 0.f, 0.f, 0.f);
            if (grow < NN) v = *(const float4 *)(A + grow * 128 + k0 + kq * 4);
            As[r][kq * 4 + 0] = f2tf(v.x);
            As[r][kq * 4 + 1] = f2tf(v.y);
            As[r][kq * 4 + 2] = f2tf(v.z);
            As[r][kq * 4 + 3] = f2tf(v.w);
        }
        // stage B: 16 k x 128 n
#pragma unroll
        for (int t = 0; t < 2; t++) {
            int idx = tid + t * 256;
            int r = idx >> 5, cq = idx & 31;
            float4 v = *(const float4 *)(B + (k0 + r) * 128 + cq * 4);
            Bs[r][cq * 4 + 0] = f2tf(v.x);
            Bs[r][cq * 4 + 1] = f2tf(v.y);
            Bs[r][cq * 4 + 2] = f2tf(v.z);
            Bs[r][cq * 4 + 3] = f2tf(v.w);
        }
        __syncthreads();
#pragma unroll
        for (int kc = 0; kc < 16; kc += 8) {
            uint32_t bf0[4], bf1[4];
#pragma unroll
            for (int nt = 0; nt < 4; nt++) {
                int col = warp_n * 32 + nt * 8 + g4;
                bf0[nt] = Bs[kc + l4][col];
                bf1[nt] = Bs[kc + l4 + 4][col];
            }
#pragma unroll
            for (int mt = 0; mt < 4; mt++) {
                int r = warp_m * 64 + mt * 16 + g4;
                uint32_t a0 = As[r][kc + l4];
                uint32_t a1 = As[r + 8][kc + l4];
                uint32_t a2 = As[r][kc + l4 + 4];
                uint32_t a3 = As[r + 8][kc + l4 + 4];
#pragma unroll
                for (int nt = 0; nt < 4; nt++) {
                    asm("mma.sync.aligned.m16n8k8.row.col.f32.tf32.tf32.f32 "
                        "{%0,%1,%2,%3}, {%4,%5,%6,%7}, {%8,%9}, {%0,%1,%2,%3};"
                        : "+f"(acc[mt][nt][0]), "+f"(acc[mt][nt][1]),
                          "+f"(acc[mt][nt][2]), "+f"(acc[mt][nt][3])
                        : "r"(a0), "r"(a1), "r"(a2), "r"(a3),
                          "r"(bf0[nt]), "r"(bf1[nt]));
                }
            }
        }
        __syncthreads();
    }

    // epilogue: store C; fused attention logits (head = warp_n)
    float asub[8], dsub[8];
    if (doLog) {
#pragma unroll
        for (int nt = 0; nt < 4; nt++) {
            int hc = nt * 8 + 2 * l4;
            asub[nt * 2 + 0] = a_s[warp_n * 32 + hc];
            asub[nt * 2 + 1] = a_s[warp_n * 32 + hc + 1];
            dsub[nt * 2 + 0] = a_d[warp_n * 32 + hc];
            dsub[nt * 2 + 1] = a_d[warp_n * 32 + hc + 1];
        }
    }
#pragma unroll
    for (int mt = 0; mt < 4; mt++) {
        int row0 = rowBase + warp_m * 64 + mt * 16 + g4;
        int row1 = row0 + 8;
        float ps0 = 0.f, pd0 = 0.f, ps1 = 0.f, pd1 = 0.f;
#pragma unroll
        for (int nt = 0; nt < 4; nt++) {
            int col = warp_n * 32 + nt * 8 + 2 * l4;
            float c0 = acc[mt][nt][0], c1 = acc[mt][nt][1];
            float c2 = acc[mt][nt][2], c3 = acc[mt][nt][3];
            if (row0 < NN) *(float2 *)(C + row0 * 128 + col) = make_float2(c0, c1);
            if (row1 < NN) *(float2 *)(C + row1 * 128 + col) = make_float2(c2, c3);
            if (doLog) {
                ps0 += c0 * asub[nt * 2] + c1 * asub[nt * 2 + 1];
                pd0 += c0 * dsub[nt * 2] + c1 * dsub[nt * 2 + 1];
                ps1 += c2 * asub[nt * 2] + c3 * asub[nt * 2 + 1];
                pd1 += c2 * dsub[nt * 2] + c3 * dsub[nt * 2 + 1];
            }
        }
        if (doLog) {
            ps0 += __shfl_xor_sync(0xffffffffu, ps0, 1);
            ps0 += __shfl_xor_sync(0xffffffffu, ps0, 2);
            pd0 += __shfl_xor_sync(0xffffffffu, pd0, 1);
            pd0 += __shfl_xor_sync(0xffffffffu, pd0, 2);
            ps1 += __shfl_xor_sync(0xffffffffu, ps1, 1);
            ps1 += __shfl_xor_sync(0xffffffffu, ps1, 2);
            pd1 += __shfl_xor_sync(0xffffffffu, pd1, 1);
            pd1 += __shfl_xor_sync(0xffffffffu, pd1, 2);
            if (l4 == 0) {
                if (row0 < NN) { g_als[row0 * 4 + warp_n] = ps0; g_ald[row0 * 4 + warp_n] = pd0; }
                if (row1 < NN) { g_als[row1 * 4 + warp_n] = ps1; g_ald[row1 * 4 + warp_n] = pd1; }
            }
        }
    }
}

// ------------- layer2 logits (H=6, C=2) ----------------------------------------
__global__ void logits2(const float *__restrict__ a_s, const float *__restrict__ a_d) {
    int t = blockIdx.x * blockDim.x + threadIdx.x;
    if (t >= NN * 6) return;
    int n = t / 6, h = t - n * 6;
    float x0 = g_xw[n * 12 + h * 2], x1 = g_xw[n * 12 + h * 2 + 1];
    g_als[t] = x0 * a_s[h * 2] + x1 * a_s[h * 2 + 1];
    g_ald[t] = x0 * a_d[h * 2] + x1 * a_d[h * 2 + 1];
}

// ============ fused node pass (layers 0/1): softmax + gather + relu ============
__global__ __launch_bounds__(256) void nodepass01(const float *__restrict__ cb,
                                                  const float *__restrict__ lb) {
    int w = (blockIdx.x * blockDim.x + threadIdx.x) >> 5;
    int lane = threadIdx.x & 31;
    if (w >= NN) return;
    int base = g_rowptr[w];
    int deg  = g_rowptr[w + 1] - base;

    int h4 = lane & 3;
    float ald_h = g_ald[w * 4 + h4];
    float mx = __int_as_float(0xFF800000);
    float sum = 0.f;

    if (deg <= 64) {
        float areg[8];
        int i = 0;
        for (int k = lane >> 2; k < deg; k += 8, i++) {
            int src = g_csrc[base + k];
            float a = g_als[src * 4 + h4] + ald_h;
            a = a > 0.f ? a : FNEG * a;
            areg[i] = a;
            mx = fmaxf(mx, a);
        }
        mx = fmaxf(mx, __shfl_xor_sync(0xffffffffu, mx, 4));
        mx = fmaxf(mx, __shfl_xor_sync(0xffffffffu, mx, 8));
        mx = fmaxf(mx, __shfl_xor_sync(0xffffffffu, mx, 16));
        i = 0;
        for (int k = lane >> 2; k < deg; k += 8, i++) {
            float e = __expf(areg[i] - mx);
            g_ebuf[(base + k) * 4 + h4] = e;
            sum += e;
        }
    } else {
        for (int k = lane >> 2; k < deg; k += 8) {
            int src = g_csrc[base + k];
            float a = g_als[src * 4 + h4] + ald_h;
            a = a > 0.f ? a : FNEG * a;
            g_ebuf[(base + k) * 4 + h4] = a;
            mx = fmaxf(mx, a);
        }
        mx = fmaxf(mx, __shfl_xor_sync(0xffffffffu, mx, 4));
        mx = fmaxf(mx, __shfl_xor_sync(0xffffffffu, mx, 8));
        mx = fmaxf(mx, __shfl_xor_sync(0xffffffffu, mx, 16));
        for (int k = lane >> 2; k < deg; k += 8) {
            float a = g_ebuf[(base + k) * 4 + h4];
            float e = __expf(a - mx);
            g_ebuf[(base + k) * 4 + h4] = e;
            sum += e;
        }
    }
    sum += __shfl_xor_sync(0xffffffffu, sum, 4);
    sum += __shfl_xor_sync(0xffffffffu, sum, 8);
    sum += __shfl_xor_sync(0xffffffffu, sum, 16);
    float inv = 1.f / sum;
    __syncwarp();

    int hc = lane >> 3;
    float cinv = __shfl_sync(0xffffffffu, inv, hc);
    float4 acc = make_float4(0.f, 0.f, 0.f, 0.f);
    int k = 0;
    for (; k + 3 < deg; k += 4) {
        int s0 = g_csrc[base + k],     s1 = g_csrc[base + k + 1];
        int s2 = g_csrc[base + k + 2], s3 = g_csrc[base + k + 3];
        float e0 = g_ebuf[(base + k) * 4 + hc];
        float e1 = g_ebuf[(base + k + 1) * 4 + hc];
        float e2 = g_ebuf[(base + k + 2) * 4 + hc];
        float e3 = g_ebuf[(base + k + 3) * 4 + hc];
        float4 v0 = *(const float4 *)(g_xw + s0 * 128 + lane * 4);
        float4 v1 = *(const float4 *)(g_xw + s1 * 128 + lane * 4);
        float4 v2 = *(const float4 *)(g_xw + s2 * 128 + lane * 4);
        float4 v3 = *(const float4 *)(g_xw + s3 * 128 + lane * 4);
        float c0 = e0 * cinv, c1 = e1 * cinv, c2 = e2 * cinv, c3 = e3 * cinv;
        acc.x += c0 * v0.x + c1 * v1.x + c2 * v2.x + c3 * v3.x;
        acc.y += c0 * v0.y + c1 * v1.y + c2 * v2.y + c3 * v3.y;
        acc.z += c0 * v0.z + c1 * v1.z + c2 * v2.z + c3 * v3.z;
        acc.w += c0 * v0.w + c1 * v1.w + c2 * v2.w + c3 * v3.w;
    }
    for (; k < deg; k++) {
        int s0 = g_csrc[base + k];
        float e0 = g_ebuf[(base + k) * 4 + hc];
        float4 v0 = *(const float4 *)(g_xw + s0 * 128 + lane * 4);
        float c0 = e0 * cinv;
        acc.x += c0 * v0.x; acc.y += c0 * v0.y;
        acc.z += c0 * v0.z; acc.w += c0 * v0.w;
    }

    int c = lane * 4;
    float4 lin = *(const float4 *)(g_acc + w * 128 + c);
    float4 b0 = *(const float4 *)(cb + c);
    float4 b1 = *(const float4 *)(lb + c);
    float4 o;
    o.x = acc.x + lin.x + b0.x + b1.x;
    o.y = acc.y + lin.y + b0.y + b1.y;
    o.z = acc.z + lin.z + b0.z + b1.z;
    o.w = acc.w + lin.w + b0.w + b1.w;
    o.x = o.x > 0.f ? o.x : 0.f;
    o.y = o.y > 0.f ? o.y : 0.f;
    o.z = o.z > 0.f ? o.z : 0.f;
    o.w = o.w > 0.f ? o.w : 0.f;
    *(float4 *)(g_h + w * 128 + c) = o;
}

// ============ fused node pass (layer 2, H=6, C=2, concat=False) ================
__global__ __launch_bounds__(256) void nodepass2(const float *__restrict__ cb,
                                                 const float *__restrict__ lb,
                                                 float *__restrict__ out) {
    int w = (blockIdx.x * blockDim.x + threadIdx.x) >> 5;
    int lane = threadIdx.x & 31;
    if (w >= NN) return;
    int base = g_rowptr[w];
    int deg  = g_rowptr[w + 1] - base;

    int h8 = lane & 7;
    bool hact = h8 < 6;
    float ald_h = hact ? g_ald[w * 6 + h8] : 0.f;
    float mx = __int_as_float(0xFF800000);
    for (int k = lane >> 3; k < deg; k += 4) {
        int src = g_csrc[base + k];
        if (hact) {
            float a = g_als[src * 6 + h8] + ald_h;
            a = a > 0.f ? a : FNEG * a;
            g_ebuf[(base + k) * 6 + h8] = a;
            mx = fmaxf(mx, a);
        }
    }
    mx = fmaxf(mx, __shfl_xor_sync(0xffffffffu, mx, 8));
    mx = fmaxf(mx, __shfl_xor_sync(0xffffffffu, mx, 16));
    float sum = 0.f;
    for (int k = lane >> 3; k < deg; k += 4) {
        if (hact) {
            float a = g_ebuf[(base + k) * 6 + h8];
            float e = __expf(a - mx);
            g_ebuf[(base + k) * 6 + h8] = e;
            sum += e;
        }
    }
    sum += __shfl_xor_sync(0xffffffffu, sum, 8);
    sum += __shfl_xor_sync(0xffffffffu, sum, 16);
    float inv = (hact && sum != 0.f) ? 1.f / sum : 0.f;
    __syncwarp();

    float cinv = __shfl_sync(0xffffffffu, inv, lane >> 1);
    float acc = 0.f;
    bool act = lane < 12;
    for (int k = 0; k < deg; k++) {
        int src = g_csrc[base + k];
        if (act) {
            float ee = g_ebuf[(base + k) * 6 + (lane >> 1)];
            float v  = g_xw[src * 12 + lane];
            acc += ee * cinv * v;
        }
    }
    float s = acc;
    s += __shfl_down_sync(0xffffffffu, s, 2);
    s += __shfl_down_sync(0xffffffffu, s, 4);
    s += __shfl_down_sync(0xffffffffu, s, 8);
    if (lane < 2)
        out[w * 2 + lane] = s * (1.f / 6.f) + cb[lane] + g_lin2[w * 2 + lane] + lb[lane];
}

// ------------- layer2 small GEMM: g_xw[N,12] = h@c2_W ; g_lin2[N,2] = h@l2_W ---
__global__ __launch_bounds__(256) void gemm_l2(const float *__restrict__ c2W,
                                               const float *__restrict__ l2W) {
    __shared__ float Ah[64][128];
    __shared__ float Ws[128 * 14];
    int tid = threadIdx.x;
    int n0 = blockIdx.x * 64;
    for (int i = tid; i < 128 * 12; i += 256) Ws[(i / 12) * 14 + (i % 12)] = c2W[i];
    for (int i = tid; i < 128 * 2;  i += 256) Ws[(i / 2) * 14 + 12 + (i % 2)] = l2W[i];
#pragma unroll
    for (int t = 0; t < 8; t++) {
        int idx = tid + t * 256;
        int r = idx >> 5, q = idx & 31;
        int n = n0 + r;
        float4 v = make_float4(0.f, 0.f, 0.f, 0.f);
        if (n < NN) v = *(const float4 *)(g_h + n * 128 + q * 4);
        *((float4 *)&Ah[r][q * 4]) = v;
    }
    __syncthreads();
    for (int o = tid; o < 64 * 14; o += 256) {
        int r = o / 14, col = o - r * 14;
        int n = n0 + r;
        if (n >= NN) continue;
        float s = 0.f;
#pragma unroll
        for (int k = 0; k < 128; k++) s += Ah[r][k] * Ws[k * 14 + col];
        if (col < 12) g_xw[n * 12 + col] = s;
        else          g_lin2[n * 2 + (col - 12)] = s;
    }
}

// ---------------- launch --------------------------------------------------------
extern "C" void kernel_launch(void *const *d_in, const int *in_sizes, int n_in,
                              void *d_out, int out_size) {
    const float *x   = (const float *)d_in[0];
    const int   *ei  = (const int *)d_in[1];
    // d_in[2] edge_attr: ignored (GATConv edge_dim=None)
    const float *c0W = (const float *)d_in[3],  *c0as = (const float *)d_in[4];
    const float *c0ad= (const float *)d_in[5],  *c0b  = (const float *)d_in[6];
    const float *l0W = (const float *)d_in[7],  *l0b  = (const float *)d_in[8];
    const float *c1W = (const float *)d_in[9],  *c1as = (const float *)d_in[10];
    const float *c1ad= (const float *)d_in[11], *c1b  = (const float *)d_in[12];
    const float *l1W = (const float *)d_in[13], *l1b  = (const float *)d_in[14];
    const float *c2W = (const float *)d_in[15], *c2as = (const float *)d_in[16];
    const float *c2ad= (const float *)d_in[17], *c2b  = (const float *)d_in[18];
    const float *l2W = (const float *)d_in[19], *l2b  = (const float *)d_in[20];
    float *out = (float *)d_out;

    dim3 gg((NN + 127) / 128, 2);
    int gN6 = (NN * 6 + 255) / 256;
    int gE4 = (ET + 1023) / 1024;       // 4 edges per thread
    int gNW = (NN * 32 + 255) / 256;    // one warp per node

    // ---- CSR build (edge structure shared by all layers) ----
    csr_zero<<<(NN + 255) / 256, 256>>>();
    csr_hist<<<gE4, 256>>>(ei);
    csr_scan<<<1, 1024>>>();
    csr_scatter<<<gE4, 256>>>(ei);

    // ---- layer 0 ----
    gemm_mma<<<gg, 256>>>(x, c0W, l0W, 1, c0as, c0ad);
    nodepass01<<<gNW, 256>>>(c0b, l0b);

    // ---- layer 1 ----
    gemm_mma<<<gg, 256>>>(x, c1W, l1W, 0, c1as, c1ad);
    nodepass01<<<gNW, 256>>>(c1b, l1b);

    // ---- layer 2 ----
    gemm_l2<<<(NN + 63) / 64, 256>>>(c2W, l2W);
    logits2<<<gN6, 256>>>(c2as, c2ad);
    nodepass2<<<gNW, 256>>>(c2b, l2b, out);
}